// round 5
// baseline (speedup 1.0000x reference)
#include <cuda_runtime.h>
#include <cuda_fp16.h>

// RC backward-Euler scan. v5:
//  - coefficients 8 B/step: b (fp32) + (h,g) packed __half2, transposed planes
//  - S=128, warm-up = 4 chunks (512 steps, same as v4 -> same accuracy)
//  - 32768 scan threads = 1024 warps (~2/SMSP): latency hiding via occupancy
//  - streaming (evict-first) output stores to protect coeff L2 residency

#define DT_S   1800.0f
#define GA     31.388f
#define S2     128
#define PWARM  4
#define NMAX   (1 << 22)

static __device__ float4 g_b4[NMAX / 4];    // 4 steps of b per entry
static __device__ uint4  g_hg4[NMAX / 4];   // 4 steps of packed (h,g) per entry

struct DCst {
    float iRie, iRea, invCin, invCen;
    float M11, nM12, nM21;
    float kD, kE, k0a, k1a;
    float gam, del, c_h, c_g1, dtCen;
};

__device__ __forceinline__ DCst make_consts(float R_ie, float R_ea,
                                            float C_in, float C_en)
{
    DCst c;
    c.iRie   = 1.0f / R_ie;
    c.iRea   = 1.0f / R_ea;
    c.invCin = 1.0f / C_in;
    c.invCen = 1.0f / C_en;
    c.M11  = 1.0f + DT_S * (c.iRea + c.iRie) * c.invCen;
    c.nM12 = DT_S * c.iRie * c.invCen;
    c.nM21 = DT_S * c.iRie * c.invCin;
    c.kD   = c.M11  / c.nM12;
    c.kE   = c.nM21 / c.nM12;
    c.k0a  = 1.0f / c.M11;
    c.k1a  = c.nM21 / c.M11;
    float alpha = 1.0f + DT_S * c.iRie * c.invCin;   // M22 = alpha + beta*u
    float beta  = DT_S * c.invCin;
    c.gam  = c.M11 * alpha - c.nM12 * c.nM21;        // det = gam + del*u
    c.del  = c.M11 * beta;
    c.c_h  = c.nM12 * DT_S * c.invCin;
    c.c_g1 = c.M11  * DT_S * c.invCin;
    c.dtCen = DT_S * c.invCen;
    return c;
}

__device__ __forceinline__ float frcp_approx(float x) {
    float r;
    asm("rcp.approx.f32 %0, %1;" : "=f"(r) : "f"(x));
    return r;
}

// ------------------------------------------- pre-pass: compute + transpose
// 256-thread block: 32(k) x 32(j) tile, each thread does 4 consecutive steps
// (one batched reciprocal per 4 elements).
__global__ void __launch_bounds__(256)
pre_t_kernel(const float* __restrict__ To,  const float* __restrict__ Irr,
             const float* __restrict__ Qint, const float* __restrict__ Qah,
             const float* __restrict__ Ria,
             const float* pR_ie, const float* pR_ea,
             const float* pC_in, const float* pC_en,
             const float* pA_si, const float* pA_se,
             const float* pA_ii, const float* pA_ie,
             int C)
{
    __shared__ float4 tb[8][33];
    __shared__ uint4  th[8][33];

    const DCst c = make_consts(__ldg(pR_ie), __ldg(pR_ea), __ldg(pC_in), __ldg(pC_en));
    float a_si = __ldg(pA_si), a_se = __ldg(pA_se);
    float a_ii = __ldg(pA_ii), a_ie = __ldg(pA_ie);

    int j0 = blockIdx.x * 32;
    int k0 = blockIdx.y * 32;

    {   // phase 1: coalesced read + compute
        int kg = threadIdx.x & 7;        // 0..7 (x4 steps)
        int jj = threadIdx.x >> 3;       // 0..31
        int t  = (j0 + jj) * S2 + k0 + 4 * kg;

        float4 to4 = *(const float4*)(To  + t);
        float4 ir4 = *(const float4*)(Irr + t);
        float4 qi4 = *(const float4*)(Qint + t);
        float4 qa4 = *(const float4*)(Qah + t);
        float4 ra4 = *(const float4*)(Ria + t);
        const float* to = (const float*)&to4;
        const float* ir = (const float*)&ir4;
        const float* qi = (const float*)&qi4;
        const float* qa = (const float*)&qa4;
        const float* ra = (const float*)&ra4;

        float Rc[4], P[4], ipv[4];
        #pragma unroll
        for (int i = 0; i < 4; ++i) {
            Rc[i] = fmaxf(ra[i], 1e-4f);
            P[i]  = fmaf(c.gam, Rc[i], c.del);
        }
        float p01 = P[0] * P[1], p23 = P[2] * P[3];
        float ipa = frcp_approx(p01 * p23);
        float i01 = ipa * p23, i23 = ipa * p01;
        ipv[0] = i01 * P[1]; ipv[1] = i01 * P[0];
        ipv[2] = i23 * P[3]; ipv[3] = i23 * P[2];
        #pragma unroll
        for (int i = 0; i < 4; ++i)      // one Newton polish
            ipv[i] = ipv[i] * fmaf(-P[i], ipv[i], 2.0f);

        float4 b4;  float* bp = (float*)&b4;
        uint4  hg4; unsigned* hp = (unsigned*)&hg4;
        #pragma unroll
        for (int i = 0; i < 4; ++i) {
            float ip  = ipv[i];
            float rp  = Rc[i] * ip;                 // invdet
            float Qs  = GA * fminf(fmaxf(ir[i], 0.0f), 2000.0f);
            float qh  = fmaxf(qa[i], 0.0f);
            float b   = c.nM12 * rp;
            float a   = fmaf(c.k1a, b, c.k0a);
            float s0  = c.dtCen * fmaf(to[i], c.iRea,
                                 fmaf(a_se, Qs, a_ie * qi[i]));
            float s1  = fmaf(a_si, Qs, fmaf(a_ii, qi[i], qh));
            float T1  = ip * fmaf(Rc[i], s1, to[i]);
            float h   = fmaf(c.c_h, T1, a * s0);
            float g   = fmaf(c.c_g1, T1, c.nM21 * (rp * s0));
            bp[i] = b;
            __half2 p = __floats2half2_rn(h, g);
            hp[i] = *reinterpret_cast<unsigned*>(&p);
        }
        tb[kg][jj] = b4;
        th[kg][jj] = hg4;
    }
    __syncthreads();
    {   // phase 2: transposed coalesced 512B writes
        int jj = threadIdx.x & 31;
        int kg = threadIdx.x >> 5;       // 0..7
        int idx = ((k0 >> 2) + kg) * C + j0 + jj;
        g_b4[idx]  = tb[kg][jj];
        g_hg4[idx] = th[kg][jj];
    }
}

// ------------------------------------------------------------- scan kernel
struct G16 { float4 b[4]; uint4 hg[4]; };

__device__ __forceinline__ void load16(G16& d, int kgBase, int col, int C) {
    #pragma unroll
    for (int i = 0; i < 4; ++i) {
        int idx = (kgBase + i) * C + col;
        d.b[i]  = __ldg(&g_b4[idx]);
        d.hg[i] = __ldg(&g_hg4[idx]);
    }
}

template<bool OUT>
__device__ __forceinline__ void process16(
    const G16& d, float& Te, float& Tin,
    float kD, float kE, float k0a, float k1a,
    float* __restrict__ outp)
{
    #pragma unroll
    for (int i = 0; i < 4; ++i) {
        const float*    bb = (const float*)&d.b[i];
        const unsigned* hh = (const unsigned*)&d.hg[i];
        float4 v;
        float* vv = (float*)&v;
        #pragma unroll
        for (int e = 0; e < 4; ++e) {
            float b = bb[e];
            unsigned hgu = hh[e];
            __half2 hg2 = *reinterpret_cast<const __half2*>(&hgu);
            float2 hg = __half22float2(hg2);
            float a  = fmaf(k1a, b, k0a);
            float dd = kD * b;
            float ee = kE * b;
            float p  = fmaf(b,  Tin, hg.x);
            float q  = fmaf(ee, Te,  hg.y);
            float Te_n  = fmaf(a,  Te,  p);
            float Tin_n = fmaf(dd, Tin, q);
            Tin_n = fminf(fmaxf(Tin_n, 5.0f), 45.0f);
            Te = Te_n; Tin = Tin_n;
            if (OUT) vv[e] = Tin;
        }
        if (OUT) __stcs((float4*)(outp + 4 * i), v);   // evict-first: protect L2
    }
}

__global__ void __launch_bounds__(128)
scan_t_kernel(float* __restrict__ out,
              const float* pR_ie, const float* pR_ea,
              const float* pC_in, const float* pC_en,
              const float* pTin0, int C)
{
    int j = blockIdx.x * 128 + threadIdx.x;
    if (j >= C) return;

    const DCst c = make_consts(__ldg(pR_ie), __ldg(pR_ea), __ldg(pC_in), __ldg(pC_en));
    float kD = c.kD, kE = c.kE, k0a = c.k0a, k1a = c.k1a;
    float Tin0 = __ldg(pTin0);

    float Te = Tin0, Tin = Tin0;

    #pragma unroll 1
    for (int seg = 0; seg <= PWARM; ++seg) {
        int col = j - PWARM + seg;
        if (col < 0) continue;               // truncated warm-up: exact from t=0
        bool isOut = (seg == PWARM);
        float* outp = out + j * S2;

        G16 A, B;
        load16(A, 0, col, C);

        #pragma unroll 1
        for (int kt = 0; kt < S2; kt += 32) {
            int kg = kt >> 2;
            load16(B, kg + 4, col, C);
            if (isOut) process16<true >(A, Te, Tin, kD, kE, k0a, k1a, outp + kt);
            else       process16<false>(A, Te, Tin, kD, kE, k0a, k1a, nullptr);
            if (kt + 32 < S2) load16(A, kg + 8, col, C);
            if (isOut) process16<true >(B, Te, Tin, kD, kE, k0a, k1a, outp + kt + 16);
            else       process16<false>(B, Te, Tin, kD, kE, k0a, k1a, nullptr);
        }
    }
}

// ------------------------------------------- exact fallback (ragged n only)
__global__ void seq_kernel(const float* __restrict__ To, const float* __restrict__ Irr,
                           const float* __restrict__ Qint, const float* __restrict__ Qah,
                           const float* __restrict__ Ria,
                           const float* pR_ie, const float* pR_ea,
                           const float* pC_in, const float* pC_en,
                           const float* pA_si, const float* pA_se,
                           const float* pA_ii, const float* pA_ie,
                           const float* pTin0,
                           float* __restrict__ out, int n)
{
    float iRie = 1.0f / *pR_ie, iRea = 1.0f / *pR_ea;
    float invCin = 1.0f / *pC_in, invCen = 1.0f / *pC_en;
    float a_si = *pA_si, a_se = *pA_se, a_ii = *pA_ii, a_ie = *pA_ie;
    float M11  = 1.0f + DT_S * (iRea + iRie) * invCen;
    float nM12 = DT_S * iRie * invCen;
    float nM21 = DT_S * iRie * invCin;
    float Te = *pTin0, Tin = *pTin0;
    for (int t = 0; t < n; ++t) {
        float Ria_c = fmaxf(Ria[t], 1e-4f);
        float u     = 1.0f / Ria_c;
        float Qsol  = GA * fminf(fmaxf(Irr[t], 0.0f), 2000.0f);
        float qah   = fmaxf(Qah[t], 0.0f);
        float M22 = 1.0f + DT_S * (u + iRie) * invCin;
        float det = M11 * M22 - nM12 * nM21;
        float invdet = 1.0f / det;
        float b0 = To[t] * iRea * invCen + (a_se * Qsol + a_ie * Qint[t]) * invCen;
        float b1 = (To[t] * u + a_si * Qsol + a_ii * Qint[t] + qah) * invCin;
        float r0 = Te + DT_S * b0;
        float r1 = Tin + DT_S * b1;
        float Te_n  = (M22 * r0 + nM12 * r1) * invdet;
        float Tin_n = (M11 * r1 + nM21 * r0) * invdet;
        Tin_n = fminf(fmaxf(Tin_n, 5.0f), 45.0f);
        Te = Te_n; Tin = Tin_n;
        out[t] = Tin_n;
    }
}

extern "C" void kernel_launch(void* const* d_in, const int* in_sizes, int n_in,
                              void* d_out, int out_size)
{
    const float* pR_ie = (const float*)d_in[0];
    const float* pR_ea = (const float*)d_in[1];
    const float* pC_in = (const float*)d_in[2];
    const float* pC_en = (const float*)d_in[3];
    const float* pA_si = (const float*)d_in[4];
    const float* pA_se = (const float*)d_in[5];
    const float* pA_ii = (const float*)d_in[6];
    const float* pA_ie = (const float*)d_in[7];
    const float* pTin0 = (const float*)d_in[8];
    const float* To   = (const float*)d_in[9];
    const float* Irr  = (const float*)d_in[10];
    const float* Qint = (const float*)d_in[11];
    const float* Qah  = (const float*)d_in[12];
    const float* Ria  = (const float*)d_in[13];
    float* out = (float*)d_out;
    int n = in_sizes[9];

    if (n > NMAX || n <= 0 || (n % S2) != 0 || ((n / S2) % 128) != 0) {
        seq_kernel<<<1, 1>>>(To, Irr, Qint, Qah, Ria,
                             pR_ie, pR_ea, pC_in, pC_en,
                             pA_si, pA_se, pA_ii, pA_ie, pTin0, out, n);
        return;
    }

    int C = n / S2;                          // 32768
    dim3 pgrid(C / 32, S2 / 32);             // (1024, 4) blocks of 256
    pre_t_kernel<<<pgrid, 256>>>(To, Irr, Qint, Qah, Ria,
                                 pR_ie, pR_ea, pC_in, pC_en,
                                 pA_si, pA_se, pA_ii, pA_ie, C);

    scan_t_kernel<<<C / 128, 128>>>(out, pR_ie, pR_ea, pC_in, pC_en, pTin0, C);
}